// round 14
// baseline (speedup 1.0000x reference)
#include <cuda_runtime.h>
#include <cuda_fp16.h>
#include <math.h>
#include <stdint.h>

// Problem constants
#define BB 4
#define SS 2048
#define DD 1024
#define HH 16
#define DH 64
#define MROWS (BB * SS)      // 8192
#define N1 (3 * DD)          // 3072

// Scratch (allocation-free: device globals), all fp16 inter-stage
__device__ __half g_qkv[(size_t)MROWS * N1];   // [B*S, 3D]
__device__ __half g_att[(size_t)MROWS * DD];   // [B*S, D]
__device__ __half g_xh [(size_t)MROWS * DD];
__device__ __half g_w1h[(size_t)N1 * DD];
__device__ __half g_w2h[(size_t)DD * DD];

// ===========================================================================
// helpers
// ===========================================================================
__device__ __forceinline__ uint32_t smem_u32(const void* p) {
    uint32_t a;
    asm("{ .reg .u64 t; cvta.to.shared.u64 t, %1; cvt.u32.u64 %0, t; }"
        : "=r"(a) : "l"(p));
    return a;
}
__device__ __forceinline__ uint32_t packh2(float a, float b) {
    __half2 h = __floats2half2_rn(a, b);
    return *reinterpret_cast<uint32_t*>(&h);
}

#define MMA_F16(acc, a0, a1, a2, a3, b0, b1) \
    asm volatile( \
        "mma.sync.aligned.m16n8k16.row.col.f32.f16.f16.f32 " \
        "{%0,%1,%2,%3}, {%4,%5,%6,%7}, {%8,%9}, {%0,%1,%2,%3};" \
        : "+f"((acc)[0]), "+f"((acc)[1]), "+f"((acc)[2]), "+f"((acc)[3]) \
        : "r"(a0), "r"(a1), "r"(a2), "r"(a3), "r"(b0), "r"(b1))

#define LDSM4(r, a) \
    asm volatile("ldmatrix.sync.aligned.m8n8.x4.shared.b16 {%0,%1,%2,%3}, [%4];" \
        : "=r"((r)[0]), "=r"((r)[1]), "=r"((r)[2]), "=r"((r)[3]) : "r"(a))
#define LDSM4T(r, a) \
    asm volatile("ldmatrix.sync.aligned.m8n8.x4.trans.shared.b16 {%0,%1,%2,%3}, [%4];" \
        : "=r"((r)[0]), "=r"((r)[1]), "=r"((r)[2]), "=r"((r)[3]) : "r"(a))

#define CP_A16(dst, src) \
    asm volatile("cp.async.cg.shared.global [%0], [%1], 16;" \
                 :: "r"(dst), "l"(src) : "memory")
#define CP_COMMIT() asm volatile("cp.async.commit_group;" ::: "memory")
#define CP_WAIT1()  asm volatile("cp.async.wait_group 1;" ::: "memory")
#define CP_WAIT0()  asm volatile("cp.async.wait_group 0;" ::: "memory")

// ===========================================================================
// fp16 conversion prep (x, w_in, w_out) — one launch
// ===========================================================================
__global__ void toh3(const float* __restrict__ x,  __half* __restrict__ xh,
                     const float* __restrict__ w1, __half* __restrict__ w1h,
                     const float* __restrict__ w2, __half* __restrict__ w2h)
{
    const int nx = MROWS * DD / 4, n1 = N1 * DD / 4, n2 = DD * DD / 4;
    int i = blockIdx.x * blockDim.x + threadIdx.x;
    const float4* s; __half2* d; int j;
    if (i < nx)            { s = (const float4*)x;  d = (__half2*)xh;  j = i; }
    else if (i < nx + n1)  { s = (const float4*)w1; d = (__half2*)w1h; j = i - nx; }
    else if (i < nx + n1 + n2) { s = (const float4*)w2; d = (__half2*)w2h; j = i - nx - n1; }
    else return;
    float4 v = s[j];
    d[2 * j + 0] = __floats2half2_rn(v.x, v.y);
    d[2 * j + 1] = __floats2half2_rn(v.z, v.w);
}

// ===========================================================================
// fp16 mma.sync GEMM: C[M,N] = A[M,K] @ B[N,K]^T + bias[N]
// NEW: CTA tile 128x256, 512 threads (16 warps, 4Mx4N), warp tile 32x64,
// BK=64, 3-stage cp.async. 6 cp.async/thread/chunk (was 8) against the same
// 64 MMAs/warp -> 25% lower LDGSTS-issue per MMA + better L2 reuse.
// ===========================================================================
#define STAGES  3
#define BKH     64
#define PADH    72
#define BM      128
#define BN      256
#define TILEHA  (BM * PADH)
#define TILEHB  (BN * PADH)
#define STAGEH  (TILEHA + TILEHB)
#define GSMEM_BYTES (STAGES * STAGEH * 2)   // 165888

template<int OUT_HALF>
__global__ __launch_bounds__(512, 1) void gemm_f16mma(
    const __half* __restrict__ A, const __half* __restrict__ Bm,
    const float* __restrict__ bias, void* __restrict__ Cv,
    int M, int N, int K)
{
    extern __shared__ __half smh[];
    const uint32_t smb = smem_u32(smh);
    const int tid  = threadIdx.x;
    const int lane = tid & 31, wid = tid >> 5;
    const int g = lane >> 2, t = lane & 3;
    const int wm = wid & 3, wn = wid >> 2;       // 4M x 4N
    const int bm = blockIdx.y * BM, bn = blockIdx.x * BN;

    const int lrow = tid >> 3;          // 0..63
    const int lseg = tid & 7;
    const __half* aBase = A  + (size_t)(bm + lrow) * K + lseg * 8;
    const __half* bBase = Bm + (size_t)(bn + lrow) * K + lseg * 8;
    const uint32_t dA = smb + (uint32_t)((lrow * PADH + lseg * 8) * 2);

    const uint32_t aAddr0 = smb + (uint32_t)(((wm * 32 + (lane & 15)) * PADH) * 2)
                          + ((lane >> 4) << 4);
    const uint32_t bAddr0 = smb + (uint32_t)((TILEHA + (wn * 64 + (lane & 15)) * PADH) * 2)
                          + ((lane >> 4) << 4);

    float acc[2][8][4];
    #pragma unroll
    for (int mt = 0; mt < 2; mt++)
        #pragma unroll
        for (int nt = 0; nt < 8; nt++)
            #pragma unroll
            for (int r = 0; r < 4; r++) acc[mt][nt][r] = 0.f;

#define ISSUE_CHUNK(c, s) do { \
    uint32_t _b = dA + (uint32_t)(s) * (STAGEH * 2); \
    const __half* _pa = aBase + (c) * BKH; \
    const __half* _pb = bBase + (c) * BKH; \
    _Pragma("unroll") \
    for (int _i = 0; _i < 2; _i++) \
        CP_A16(_b + _i * (64 * PADH * 2), _pa + (size_t)_i * 64 * K); \
    _Pragma("unroll") \
    for (int _i = 0; _i < 4; _i++) \
        CP_A16(_b + TILEHA * 2 + _i * (64 * PADH * 2), _pb + (size_t)_i * 64 * K); \
    CP_COMMIT(); \
} while (0)

#define LOAD_FRAGS(af, bq, soff, ks) do { \
    const uint32_t _ko = (soff) + (ks) * 32; \
    LDSM4((af)[0], aAddr0 + _ko); \
    LDSM4((af)[1], aAddr0 + _ko + 16 * PADH * 2); \
    _Pragma("unroll") \
    for (int _p = 0; _p < 4; _p++) \
        LDSM4((bq)[_p], bAddr0 + _ko + _p * (16 * PADH * 2)); \
} while (0)

#define DO_MMAS(af, bq) do { \
    _Pragma("unroll") \
    for (int _mt = 0; _mt < 2; _mt++) \
        _Pragma("unroll") \
        for (int _nt = 0; _nt < 8; _nt++) \
            MMA_F16(acc[_mt][_nt], \
                    (af)[_mt][0], (af)[_mt][1], (af)[_mt][2], (af)[_mt][3], \
                    (bq)[_nt >> 1][_nt & 1], (bq)[_nt >> 1][2 + (_nt & 1)]); \
} while (0)

    const int NCH = K / BKH;   // 16
    ISSUE_CHUNK(0, 0);
    ISSUE_CHUNK(1, 1);

    uint32_t afP[2][2][4], bqP[2][4][4];

    for (int c = 0; c < NCH; c++) {
        if (c + 1 < NCH) { CP_WAIT1(); } else { CP_WAIT0(); }
        __syncthreads();
        if (c + 2 < NCH) ISSUE_CHUNK(c + 2, (c + 2) % STAGES);
        const uint32_t soff = (uint32_t)((c % STAGES) * (STAGEH * 2));

        LOAD_FRAGS(afP[0], bqP[0], soff, 0);
        #pragma unroll
        for (int s = 0; s < 4; s++) {
            const int cur = s & 1, nxt = cur ^ 1;
            if (s < 3) LOAD_FRAGS(afP[nxt], bqP[nxt], soff, s + 1);
            DO_MMAS(afP[cur], bqP[cur]);
        }
    }
#undef ISSUE_CHUNK
#undef LOAD_FRAGS
#undef DO_MMAS

    const int col0 = bn + wn * 64;
    #pragma unroll
    for (int mt = 0; mt < 2; mt++) {
        #pragma unroll
        for (int h = 0; h < 2; h++) {
            int row = bm + wm * 32 + mt * 16 + g + h * 8;
            #pragma unroll
            for (int nt = 0; nt < 8; nt++) {
                int cc = nt * 8 + t * 2;
                float2 bz = *(const float2*)(bias + col0 + cc);
                float vx = acc[mt][nt][h * 2 + 0] + bz.x;
                float vy = acc[mt][nt][h * 2 + 1] + bz.y;
                if (OUT_HALF) {
                    __half* cp = (__half*)Cv + (size_t)row * N + col0 + cc;
                    *(__half2*)cp = __floats2half2_rn(vx, vy);
                } else {
                    float* cp = (float*)Cv + (size_t)row * N + col0 + cc;
                    *(float2*)cp = make_float2(vx, vy);
                }
            }
        }
    }
}

// ===========================================================================
// fp16 tensor-core flash attention (R10 structure; NEW: skip O-rescale when
// the running max is unchanged — multiply-by-1 eliminated, bit-identical).
// ===========================================================================
#define QT  128
#define KT2 128
#define APD 72
#define AK_OFF(s) (QT * APD + (s) * KT2 * APD)
#define AV_OFF(s) (QT * APD + 2 * KT2 * APD + (s) * KT2 * APD)
#define ASMEM_BYTES ((QT * APD + 4 * KT2 * APD) * 2)   // 92160

__global__ __launch_bounds__(256, 2) void flash_attn_f16(const int* __restrict__ causal_flag)
{
    extern __shared__ __half smh[];
    const uint32_t sb = smem_u32(smh);
    __half* Ps = smh;

    const int qt = gridDim.x - 1 - blockIdx.x;
    const int h = blockIdx.y, b = blockIdx.z;
    const int tid = threadIdx.x, lane = tid & 31, w = tid >> 5;
    const int g = lane >> 2, t = lane & 3;
    const int causal = *causal_flag;
    const int r0 = w * 16 + g, r1 = r0 + 8;
    const int rowmin = qt * QT + w * 16;

    const int ktmax = causal ? qt : (SS / KT2 - 1);
    const __half* kvb = g_qkv + (size_t)(b * SS) * N1 + DD + h * DH;
    const int irow = tid >> 3;
    const int iseg = tid & 7;

    const uint32_t pAddr = sb + (uint32_t)(((w * 16 + (lane & 15)) * APD) * 2)
                         + ((lane >> 4) << 4);
    const uint32_t kAddr = sb + (uint32_t)((AK_OFF(0) + (lane & 15) * APD) * 2)
                         + ((lane >> 4) << 4);
    const uint32_t vAddr = sb + (uint32_t)((AV_OFF(0) + (lane & 15) * APD) * 2)
                         + ((lane >> 4) << 4);

#define ISSUE_KV(kt, s) do { \
    const __half* _kb = kvb + (size_t)((kt) * KT2) * N1; \
    uint32_t _kd = sb + (uint32_t)(AK_OFF(s) * 2); \
    uint32_t _vd = sb + (uint32_t)(AV_OFF(s) * 2); \
    _Pragma("unroll") \
    for (int _i = 0; _i < 4; _i++) { \
        int _r = irow + _i * 32; \
        const __half* _src = _kb + (size_t)_r * N1 + iseg * 8; \
        CP_A16(_kd + (uint32_t)((_r * APD + iseg * 8) * 2), _src); \
        CP_A16(_vd + (uint32_t)((_r * APD + iseg * 8) * 2), _src + DD); \
    } \
    CP_COMMIT(); \
} while (0)

    ISSUE_KV(0, 0);

    {
        const __half2 qs2 = __float2half2_rn(0.125f * 1.4426950408889634f);
        const __half* qb = g_qkv + (size_t)(b * SS + qt * QT) * N1 + h * DH;
        #pragma unroll
        for (int i = 0; i < 4; i++) {
            int fid = tid + i * 256, row = fid >> 3, c8 = fid & 7;
            __half2 v[4];
            *(uint4*)v = *(const uint4*)(qb + (size_t)row * N1 + c8 * 8);
            v[0] = __hmul2(v[0], qs2); v[1] = __hmul2(v[1], qs2);
            v[2] = __hmul2(v[2], qs2); v[3] = __hmul2(v[3], qs2);
            *(uint4*)(Ps + row * APD + c8 * 8) = *(uint4*)v;
        }
    }
    __syncthreads();
    uint32_t qf[4][4];
    #pragma unroll
    for (int ks = 0; ks < 4; ks++) LDSM4(qf[ks], pAddr + ks * 32);

    float m0 = -INFINITY, m1 = -INFINITY;
    float l0 = 0.f, l1 = 0.f;
    float oa[8][4];
    #pragma unroll
    for (int nt = 0; nt < 8; nt++)
        #pragma unroll
        for (int r = 0; r < 4; r++) oa[nt][r] = 0.f;

    for (int kt = 0; kt <= ktmax; kt++) {
        const int cur = kt & 1;
        CP_WAIT0();
        __syncthreads();
        if (kt < ktmax) ISSUE_KV(kt + 1, cur ^ 1);

        const uint32_t tileK = kAddr + (uint32_t)(cur * (KT2 * APD * 2));
        const uint32_t tileV = vAddr + (uint32_t)(cur * (KT2 * APD * 2));

        #pragma unroll
        for (int half = 0; half < 2; half++) {
            const int keybase = kt * KT2 + half * 64;
            if (causal && keybase > rowmin + 15) continue;

            const uint32_t bufK = tileK + (uint32_t)(half * (64 * APD * 2));
            const uint32_t bufV = tileV + (uint32_t)(half * (64 * APD * 2));

            float sc[8][4];
            #pragma unroll
            for (int nt = 0; nt < 8; nt++)
                #pragma unroll
                for (int r = 0; r < 4; r++) sc[nt][r] = 0.f;
            #pragma unroll
            for (int ks = 0; ks < 4; ks++) {
                uint32_t kb[4][4];
                #pragma unroll
                for (int p = 0; p < 4; p++)
                    LDSM4(kb[p], bufK + ks * 32 + p * (16 * APD * 2));
                #pragma unroll
                for (int nt = 0; nt < 8; nt++)
                    MMA_F16(sc[nt], qf[ks][0], qf[ks][1], qf[ks][2], qf[ks][3],
                            kb[nt >> 1][nt & 1], kb[nt >> 1][2 + (nt & 1)]);
            }

            if (causal && keybase + 63 > rowmin) {
                const int r0g = rowmin + g, r1g = r0g + 8;
                #pragma unroll
                for (int nt = 0; nt < 8; nt++) {
                    int c0 = keybase + nt * 8 + 2 * t, c1 = c0 + 1;
                    if (c0 > r0g) sc[nt][0] = -INFINITY;
                    if (c1 > r0g) sc[nt][1] = -INFINITY;
                    if (c0 > r1g) sc[nt][2] = -INFINITY;
                    if (c1 > r1g) sc[nt][3] = -INFINITY;
                }
            }

            float mx0 = m0, mx1 = m1;
            #pragma unroll
            for (int nt = 0; nt < 8; nt++) {
                mx0 = fmaxf(mx0, fmaxf(sc[nt][0], sc[nt][1]));
                mx1 = fmaxf(mx1, fmaxf(sc[nt][2], sc[nt][3]));
            }
            mx0 = fmaxf(mx0, __shfl_xor_sync(0xffffffffu, mx0, 1));
            mx0 = fmaxf(mx0, __shfl_xor_sync(0xffffffffu, mx0, 2));
            mx1 = fmaxf(mx1, __shfl_xor_sync(0xffffffffu, mx1, 1));
            mx1 = fmaxf(mx1, __shfl_xor_sync(0xffffffffu, mx1, 2));
            float a0 = exp2f(m0 - mx0), a1 = exp2f(m1 - mx1);
            m0 = mx0; m1 = mx1;

            float s0 = 0.f, s1 = 0.f;
            uint32_t ph[8][2];
            #pragma unroll
            for (int nt = 0; nt < 8; nt++) {
                float p00 = exp2f(sc[nt][0] - m0);
                float p01 = exp2f(sc[nt][1] - m0);
                float p10 = exp2f(sc[nt][2] - m1);
                float p11 = exp2f(sc[nt][3] - m1);
                s0 += p00 + p01; s1 += p10 + p11;
                ph[nt][0] = packh2(p00, p01);
                ph[nt][1] = packh2(p10, p11);
            }
            if (!(a0 == 1.f && a1 == 1.f)) {   // skip no-op rescale
                #pragma unroll
                for (int nt = 0; nt < 8; nt++) {
                    oa[nt][0] *= a0; oa[nt][1] *= a0;
                    oa[nt][2] *= a1; oa[nt][3] *= a1;
                }
            }
            l0 = l0 * a0 + s0;
            l1 = l1 * a1 + s1;

            #pragma unroll
            for (int ks = 0; ks < 4; ks++) {
                const uint32_t pf0 = ph[2 * ks][0],     pf1 = ph[2 * ks][1];
                const uint32_t pf2 = ph[2 * ks + 1][0], pf3 = ph[2 * ks + 1][1];
                #pragma unroll
                for (int j = 0; j < 4; j++) {
                    uint32_t vq[4];
                    LDSM4T(vq, bufV + ks * (16 * APD * 2) + j * 32);
                    MMA_F16(oa[2 * j + 0], pf0, pf1, pf2, pf3, vq[0], vq[1]);
                    MMA_F16(oa[2 * j + 1], pf0, pf1, pf2, pf3, vq[2], vq[3]);
                }
            }
        }
    }
#undef ISSUE_KV

    l0 += __shfl_xor_sync(0xffffffffu, l0, 1);
    l0 += __shfl_xor_sync(0xffffffffu, l0, 2);
    l1 += __shfl_xor_sync(0xffffffffu, l1, 1);
    l1 += __shfl_xor_sync(0xffffffffu, l1, 2);

    float i0 = 1.f / l0, i1 = 1.f / l1;
    __half* ob = g_att + (size_t)(b * SS + qt * QT) * DD + h * DH;
    #pragma unroll
    for (int nt = 0; nt < 8; nt++) {
        *(__half2*)(ob + (size_t)r0 * DD + nt * 8 + 2 * t) =
            __floats2half2_rn(oa[nt][0] * i0, oa[nt][1] * i0);
        *(__half2*)(ob + (size_t)r1 * DD + nt * 8 + 2 * t) =
            __floats2half2_rn(oa[nt][2] * i1, oa[nt][3] * i1);
    }
}

// ---------------------------------------------------------------------------
extern "C" void kernel_launch(void* const* d_in, const int* in_sizes, int n_in,
                              void* d_out, int out_size)
{
    const float* x     = (const float*)d_in[0];
    const float* w_in  = (const float*)d_in[1];
    const float* b_in  = (const float*)d_in[2];
    const float* w_out = (const float*)d_in[3];
    const float* b_out = (const float*)d_in[4];
    const int*   cmask = (const int*)d_in[5];

    __half *qkv, *att, *xh, *w1h, *w2h;
    cudaGetSymbolAddress((void**)&qkv, g_qkv);
    cudaGetSymbolAddress((void**)&att, g_att);
    cudaGetSymbolAddress((void**)&xh,  g_xh);
    cudaGetSymbolAddress((void**)&w1h, g_w1h);
    cudaGetSymbolAddress((void**)&w2h, g_w2h);

    cudaFuncSetAttribute((const void*)gemm_f16mma<1>,
                         cudaFuncAttributeMaxDynamicSharedMemorySize, GSMEM_BYTES);
    cudaFuncSetAttribute((const void*)gemm_f16mma<0>,
                         cudaFuncAttributeMaxDynamicSharedMemorySize, GSMEM_BYTES);
    cudaFuncSetAttribute((const void*)flash_attn_f16,
                         cudaFuncAttributeMaxDynamicSharedMemorySize, ASMEM_BYTES);

    // 0) convert x, w_in, w_out to fp16 (one launch)
    {
        int tot = MROWS * DD / 4 + N1 * DD / 4 + DD * DD / 4;
        toh3<<<(tot + 255) / 256, 256>>>(x, xh, w_in, w1h, w_out, w2h);
    }

    // 1) QKV projection -> fp16 qkv   (CTA tile 128x256)
    gemm_f16mma<1><<<dim3(N1 / BN, MROWS / BM), 512, GSMEM_BYTES>>>(
        xh, w1h, b_in, qkv, MROWS, N1, DD);

    // 2) Causal multi-head flash attention (fp16 TC, 128-key tiles)
    flash_attn_f16<<<dim3(SS / QT, HH, BB), 256, ASMEM_BYTES>>>(cmask);

    // 3) Output projection -> fp32 out
    gemm_f16mma<0><<<dim3(DD / BN, MROWS / BM), 512, GSMEM_BYTES>>>(
        att, w2h, b_out, (float*)d_out, MROWS, DD, DD);
}

// round 15
// speedup vs baseline: 1.0685x; 1.0685x over previous
#include <cuda_runtime.h>
#include <cuda_fp16.h>
#include <math.h>
#include <stdint.h>

// Problem constants
#define BB 4
#define SS 2048
#define DD 1024
#define HH 16
#define DH 64
#define MROWS (BB * SS)      // 8192
#define N1 (3 * DD)          // 3072

// Scratch (allocation-free: device globals), all fp16 inter-stage
__device__ __half g_qkv[(size_t)MROWS * N1];   // [B*S, 3D]
__device__ __half g_att[(size_t)MROWS * DD];   // [B*S, D]
__device__ __half g_xh [(size_t)MROWS * DD];
__device__ __half g_w1h[(size_t)N1 * DD];
__device__ __half g_w2h[(size_t)DD * DD];

// ===========================================================================
// helpers
// ===========================================================================
__device__ __forceinline__ uint32_t smem_u32(const void* p) {
    uint32_t a;
    asm("{ .reg .u64 t; cvta.to.shared.u64 t, %1; cvt.u32.u64 %0, t; }"
        : "=r"(a) : "l"(p));
    return a;
}
// pack two floats to f16x2 and apply ex2 in half precision (one MUFU op / pair)
__device__ __forceinline__ uint32_t exp2_h2(float a, float b) {
    uint32_t r;
    asm("{ .reg .b32 t; cvt.rn.f16x2.f32 t, %2, %1;\n\t"
        "ex2.approx.f16x2 %0, t; }"
        : "=r"(r) : "f"(a), "f"(b));
    return r;
}

#define MMA_F16(acc, a0, a1, a2, a3, b0, b1) \
    asm volatile( \
        "mma.sync.aligned.m16n8k16.row.col.f32.f16.f16.f32 " \
        "{%0,%1,%2,%3}, {%4,%5,%6,%7}, {%8,%9}, {%0,%1,%2,%3};" \
        : "+f"((acc)[0]), "+f"((acc)[1]), "+f"((acc)[2]), "+f"((acc)[3]) \
        : "r"(a0), "r"(a1), "r"(a2), "r"(a3), "r"(b0), "r"(b1))

#define LDSM4(r, a) \
    asm volatile("ldmatrix.sync.aligned.m8n8.x4.shared.b16 {%0,%1,%2,%3}, [%4];" \
        : "=r"((r)[0]), "=r"((r)[1]), "=r"((r)[2]), "=r"((r)[3]) : "r"(a))
#define LDSM4T(r, a) \
    asm volatile("ldmatrix.sync.aligned.m8n8.x4.trans.shared.b16 {%0,%1,%2,%3}, [%4];" \
        : "=r"((r)[0]), "=r"((r)[1]), "=r"((r)[2]), "=r"((r)[3]) : "r"(a))

#define CP_A16(dst, src) \
    asm volatile("cp.async.cg.shared.global [%0], [%1], 16;" \
                 :: "r"(dst), "l"(src) : "memory")
#define CP_COMMIT() asm volatile("cp.async.commit_group;" ::: "memory")
#define CP_WAIT1()  asm volatile("cp.async.wait_group 1;" ::: "memory")
#define CP_WAIT0()  asm volatile("cp.async.wait_group 0;" ::: "memory")

// ===========================================================================
// fp16 conversion prep (x, w_in, w_out) — one launch
// ===========================================================================
__global__ void toh3(const float* __restrict__ x,  __half* __restrict__ xh,
                     const float* __restrict__ w1, __half* __restrict__ w1h,
                     const float* __restrict__ w2, __half* __restrict__ w2h)
{
    const int nx = MROWS * DD / 4, n1 = N1 * DD / 4, n2 = DD * DD / 4;
    int i = blockIdx.x * blockDim.x + threadIdx.x;
    const float4* s; __half2* d; int j;
    if (i < nx)            { s = (const float4*)x;  d = (__half2*)xh;  j = i; }
    else if (i < nx + n1)  { s = (const float4*)w1; d = (__half2*)w1h; j = i - nx; }
    else if (i < nx + n1 + n2) { s = (const float4*)w2; d = (__half2*)w2h; j = i - nx - n1; }
    else return;
    float4 v = s[j];
    d[2 * j + 0] = __floats2half2_rn(v.x, v.y);
    d[2 * j + 1] = __floats2half2_rn(v.z, v.w);
}

// ===========================================================================
// fp16 mma.sync GEMM (FROZEN at R12 config): C = A @ B^T + bias
// CTA 128x128, BK=64 halfs, 3-stage cp.async, 8 warps (4Mx2N),
// warp tile 32x64, mma.m16n8k16, fp32 accumulate, reg ping-pong frags.
// ===========================================================================
#define STAGES  3
#define BKH     64
#define PADH    72
#define TILEH   (128 * PADH)
#define STAGEH  (2 * TILEH)
#define GSMEM_BYTES (STAGES * STAGEH * 2)   // 110592

template<int OUT_HALF>
__global__ __launch_bounds__(256, 2) void gemm_f16mma(
    const __half* __restrict__ A, const __half* __restrict__ Bm,
    const float* __restrict__ bias, void* __restrict__ Cv,
    int M, int N, int K)
{
    extern __shared__ __half smh[];
    const uint32_t smb = smem_u32(smh);
    const int tid  = threadIdx.x;
    const int lane = tid & 31, wid = tid >> 5;
    const int g = lane >> 2, t = lane & 3;
    const int wm = wid & 3, wn = wid >> 2;
    const int bm = blockIdx.y * 128, bn = blockIdx.x * 128;

    const int lrow = tid >> 3;
    const int lseg = tid & 7;
    const __half* aBase = A  + (size_t)(bm + lrow) * K + lseg * 8;
    const __half* bBase = Bm + (size_t)(bn + lrow) * K + lseg * 8;
    const uint32_t dA = smb + (uint32_t)((lrow * PADH + lseg * 8) * 2);

    const uint32_t aAddr0 = smb + (uint32_t)(((wm * 32 + (lane & 15)) * PADH) * 2)
                          + ((lane >> 4) << 4);
    const uint32_t bAddr0 = smb + (uint32_t)((TILEH + (wn * 64 + (lane & 15)) * PADH) * 2)
                          + ((lane >> 4) << 4);

    float acc[2][8][4];
    #pragma unroll
    for (int mt = 0; mt < 2; mt++)
        #pragma unroll
        for (int nt = 0; nt < 8; nt++)
            #pragma unroll
            for (int r = 0; r < 4; r++) acc[mt][nt][r] = 0.f;

#define ISSUE_CHUNK(c, s) do { \
    uint32_t _b = dA + (uint32_t)(s) * (STAGEH * 2); \
    const __half* _pa = aBase + (c) * BKH; \
    const __half* _pb = bBase + (c) * BKH; \
    _Pragma("unroll") \
    for (int _i = 0; _i < 4; _i++) { \
        CP_A16(_b + _i * (32 * PADH * 2),             _pa + (size_t)_i * 32 * K); \
        CP_A16(_b + TILEH * 2 + _i * (32 * PADH * 2), _pb + (size_t)_i * 32 * K); \
    } \
    CP_COMMIT(); \
} while (0)

#define LOAD_FRAGS(af, bq, soff, ks) do { \
    const uint32_t _ko = (soff) + (ks) * 32; \
    LDSM4((af)[0], aAddr0 + _ko); \
    LDSM4((af)[1], aAddr0 + _ko + 16 * PADH * 2); \
    _Pragma("unroll") \
    for (int _p = 0; _p < 4; _p++) \
        LDSM4((bq)[_p], bAddr0 + _ko + _p * (16 * PADH * 2)); \
} while (0)

#define DO_MMAS(af, bq) do { \
    _Pragma("unroll") \
    for (int _mt = 0; _mt < 2; _mt++) \
        _Pragma("unroll") \
        for (int _nt = 0; _nt < 8; _nt++) \
            MMA_F16(acc[_mt][_nt], \
                    (af)[_mt][0], (af)[_mt][1], (af)[_mt][2], (af)[_mt][3], \
                    (bq)[_nt >> 1][_nt & 1], (bq)[_nt >> 1][2 + (_nt & 1)]); \
} while (0)

    const int NCH = K / BKH;   // 16
    ISSUE_CHUNK(0, 0);
    ISSUE_CHUNK(1, 1);

    uint32_t afP[2][2][4], bqP[2][4][4];

    for (int c = 0; c < NCH; c++) {
        if (c + 1 < NCH) { CP_WAIT1(); } else { CP_WAIT0(); }
        __syncthreads();
        if (c + 2 < NCH) ISSUE_CHUNK(c + 2, (c + 2) % STAGES);
        const uint32_t soff = (uint32_t)((c % STAGES) * (STAGEH * 2));

        LOAD_FRAGS(afP[0], bqP[0], soff, 0);
        #pragma unroll
        for (int s = 0; s < 4; s++) {
            const int cur = s & 1, nxt = cur ^ 1;
            if (s < 3) LOAD_FRAGS(afP[nxt], bqP[nxt], soff, s + 1);
            DO_MMAS(afP[cur], bqP[cur]);
        }
    }
#undef ISSUE_CHUNK
#undef LOAD_FRAGS
#undef DO_MMAS

    const int col0 = bn + wn * 64;
    #pragma unroll
    for (int mt = 0; mt < 2; mt++) {
        #pragma unroll
        for (int h = 0; h < 2; h++) {
            int row = bm + wm * 32 + mt * 16 + g + h * 8;
            #pragma unroll
            for (int nt = 0; nt < 8; nt++) {
                int cc = nt * 8 + t * 2;
                float2 bz = *(const float2*)(bias + col0 + cc);
                float vx = acc[mt][nt][h * 2 + 0] + bz.x;
                float vy = acc[mt][nt][h * 2 + 1] + bz.y;
                if (OUT_HALF) {
                    __half* cp = (__half*)Cv + (size_t)row * N + col0 + cc;
                    *(__half2*)cp = __floats2half2_rn(vx, vy);
                } else {
                    float* cp = (float*)Cv + (size_t)row * N + col0 + cc;
                    *(float2*)cp = make_float2(vx, vy);
                }
            }
        }
    }
}

// ===========================================================================
// fp16 tensor-core flash attention (R12 structure).
// NEW: softmax exp via ex2.approx.f16x2 — one MUFU op yields an fp16 P pair
// already in PV A-fragment packing; row-sum recovered in fp32.
// ===========================================================================
#define QT  128
#define KT2 128
#define APD 72
#define AK_OFF(s) (QT * APD + (s) * KT2 * APD)
#define AV_OFF(s) (QT * APD + 2 * KT2 * APD + (s) * KT2 * APD)
#define ASMEM_BYTES ((QT * APD + 4 * KT2 * APD) * 2)   // 92160

__global__ __launch_bounds__(256, 2) void flash_attn_f16(const int* __restrict__ causal_flag)
{
    extern __shared__ __half smh[];
    const uint32_t sb = smem_u32(smh);
    __half* Ps = smh;

    const int qt = gridDim.x - 1 - blockIdx.x;   // LPT: heavy CTAs first
    const int h = blockIdx.y, b = blockIdx.z;
    const int tid = threadIdx.x, lane = tid & 31, w = tid >> 5;
    const int g = lane >> 2, t = lane & 3;
    const int causal = *causal_flag;
    const int r0 = w * 16 + g, r1 = r0 + 8;
    const int rowmin = qt * QT + w * 16;

    const int ktmax = causal ? qt : (SS / KT2 - 1);
    const __half* kvb = g_qkv + (size_t)(b * SS) * N1 + DD + h * DH;
    const int irow = tid >> 3;
    const int iseg = tid & 7;

    const uint32_t pAddr = sb + (uint32_t)(((w * 16 + (lane & 15)) * APD) * 2)
                         + ((lane >> 4) << 4);
    const uint32_t kAddr = sb + (uint32_t)((AK_OFF(0) + (lane & 15) * APD) * 2)
                         + ((lane >> 4) << 4);
    const uint32_t vAddr = sb + (uint32_t)((AV_OFF(0) + (lane & 15) * APD) * 2)
                         + ((lane >> 4) << 4);

#define ISSUE_KV(kt, s) do { \
    const __half* _kb = kvb + (size_t)((kt) * KT2) * N1; \
    uint32_t _kd = sb + (uint32_t)(AK_OFF(s) * 2); \
    uint32_t _vd = sb + (uint32_t)(AV_OFF(s) * 2); \
    _Pragma("unroll") \
    for (int _i = 0; _i < 4; _i++) { \
        int _r = irow + _i * 32; \
        const __half* _src = _kb + (size_t)_r * N1 + iseg * 8; \
        CP_A16(_kd + (uint32_t)((_r * APD + iseg * 8) * 2), _src); \
        CP_A16(_vd + (uint32_t)((_r * APD + iseg * 8) * 2), _src + DD); \
    } \
    CP_COMMIT(); \
} while (0)

    ISSUE_KV(0, 0);

    {
        const __half2 qs2 = __float2half2_rn(0.125f * 1.4426950408889634f);
        const __half* qb = g_qkv + (size_t)(b * SS + qt * QT) * N1 + h * DH;
        #pragma unroll
        for (int i = 0; i < 4; i++) {
            int fid = tid + i * 256, row = fid >> 3, c8 = fid & 7;
            __half2 v[4];
            *(uint4*)v = *(const uint4*)(qb + (size_t)row * N1 + c8 * 8);
            v[0] = __hmul2(v[0], qs2); v[1] = __hmul2(v[1], qs2);
            v[2] = __hmul2(v[2], qs2); v[3] = __hmul2(v[3], qs2);
            *(uint4*)(Ps + row * APD + c8 * 8) = *(uint4*)v;
        }
    }
    __syncthreads();
    uint32_t qf[4][4];
    #pragma unroll
    for (int ks = 0; ks < 4; ks++) LDSM4(qf[ks], pAddr + ks * 32);

    float m0 = -INFINITY, m1 = -INFINITY;
    float l0 = 0.f, l1 = 0.f;
    float oa[8][4];
    #pragma unroll
    for (int nt = 0; nt < 8; nt++)
        #pragma unroll
        for (int r = 0; r < 4; r++) oa[nt][r] = 0.f;

    for (int kt = 0; kt <= ktmax; kt++) {
        const int cur = kt & 1;
        CP_WAIT0();
        __syncthreads();
        if (kt < ktmax) ISSUE_KV(kt + 1, cur ^ 1);

        const uint32_t tileK = kAddr + (uint32_t)(cur * (KT2 * APD * 2));
        const uint32_t tileV = vAddr + (uint32_t)(cur * (KT2 * APD * 2));

        #pragma unroll
        for (int half = 0; half < 2; half++) {
            const int keybase = kt * KT2 + half * 64;
            if (causal && keybase > rowmin + 15) continue;

            const uint32_t bufK = tileK + (uint32_t)(half * (64 * APD * 2));
            const uint32_t bufV = tileV + (uint32_t)(half * (64 * APD * 2));

            float sc[8][4];
            #pragma unroll
            for (int nt = 0; nt < 8; nt++)
                #pragma unroll
                for (int r = 0; r < 4; r++) sc[nt][r] = 0.f;
            #pragma unroll
            for (int ks = 0; ks < 4; ks++) {
                uint32_t kb[4][4];
                #pragma unroll
                for (int p = 0; p < 4; p++)
                    LDSM4(kb[p], bufK + ks * 32 + p * (16 * APD * 2));
                #pragma unroll
                for (int nt = 0; nt < 8; nt++)
                    MMA_F16(sc[nt], qf[ks][0], qf[ks][1], qf[ks][2], qf[ks][3],
                            kb[nt >> 1][nt & 1], kb[nt >> 1][2 + (nt & 1)]);
            }

            if (causal && keybase + 63 > rowmin) {
                const int r0g = rowmin + g, r1g = r0g + 8;
                #pragma unroll
                for (int nt = 0; nt < 8; nt++) {
                    int c0 = keybase + nt * 8 + 2 * t, c1 = c0 + 1;
                    if (c0 > r0g) sc[nt][0] = -INFINITY;
                    if (c1 > r0g) sc[nt][1] = -INFINITY;
                    if (c0 > r1g) sc[nt][2] = -INFINITY;
                    if (c1 > r1g) sc[nt][3] = -INFINITY;
                }
            }

            float mx0 = m0, mx1 = m1;
            #pragma unroll
            for (int nt = 0; nt < 8; nt++) {
                mx0 = fmaxf(mx0, fmaxf(sc[nt][0], sc[nt][1]));
                mx1 = fmaxf(mx1, fmaxf(sc[nt][2], sc[nt][3]));
            }
            mx0 = fmaxf(mx0, __shfl_xor_sync(0xffffffffu, mx0, 1));
            mx0 = fmaxf(mx0, __shfl_xor_sync(0xffffffffu, mx0, 2));
            mx1 = fmaxf(mx1, __shfl_xor_sync(0xffffffffu, mx1, 1));
            mx1 = fmaxf(mx1, __shfl_xor_sync(0xffffffffu, mx1, 2));
            float a0 = exp2f(m0 - mx0), a1 = exp2f(m1 - mx1);
            m0 = mx0; m1 = mx1;

            float s0 = 0.f, s1 = 0.f;
            uint32_t ph[8][2];
            #pragma unroll
            for (int nt = 0; nt < 8; nt++) {
                // fp16x2 exp: one MUFU per P pair, result already PV-A packed
                ph[nt][0] = exp2_h2(sc[nt][0] - m0, sc[nt][1] - m0);
                ph[nt][1] = exp2_h2(sc[nt][2] - m1, sc[nt][3] - m1);
                float2 f0 = __half22float2(*reinterpret_cast<__half2*>(&ph[nt][0]));
                float2 f1 = __half22float2(*reinterpret_cast<__half2*>(&ph[nt][1]));
                s0 += f0.x + f0.y; s1 += f1.x + f1.y;
                oa[nt][0] *= a0; oa[nt][1] *= a0;
                oa[nt][2] *= a1; oa[nt][3] *= a1;
            }
            l0 = l0 * a0 + s0;
            l1 = l1 * a1 + s1;

            #pragma unroll
            for (int ks = 0; ks < 4; ks++) {
                const uint32_t pf0 = ph[2 * ks][0],     pf1 = ph[2 * ks][1];
                const uint32_t pf2 = ph[2 * ks + 1][0], pf3 = ph[2 * ks + 1][1];
                #pragma unroll
                for (int j = 0; j < 4; j++) {
                    uint32_t vq[4];
                    LDSM4T(vq, bufV + ks * (16 * APD * 2) + j * 32);
                    MMA_F16(oa[2 * j + 0], pf0, pf1, pf2, pf3, vq[0], vq[1]);
                    MMA_F16(oa[2 * j + 1], pf0, pf1, pf2, pf3, vq[2], vq[3]);
                }
            }
        }
    }
#undef ISSUE_KV

    l0 += __shfl_xor_sync(0xffffffffu, l0, 1);
    l0 += __shfl_xor_sync(0xffffffffu, l0, 2);
    l1 += __shfl_xor_sync(0xffffffffu, l1, 1);
    l1 += __shfl_xor_sync(0xffffffffu, l1, 2);

    float i0 = 1.f / l0, i1 = 1.f / l1;
    __half* ob = g_att + (size_t)(b * SS + qt * QT) * DD + h * DH;
    #pragma unroll
    for (int nt = 0; nt < 8; nt++) {
        *(__half2*)(ob + (size_t)r0 * DD + nt * 8 + 2 * t) =
            __floats2half2_rn(oa[nt][0] * i0, oa[nt][1] * i0);
        *(__half2*)(ob + (size_t)r1 * DD + nt * 8 + 2 * t) =
            __floats2half2_rn(oa[nt][2] * i1, oa[nt][3] * i1);
    }
}

// ---------------------------------------------------------------------------
extern "C" void kernel_launch(void* const* d_in, const int* in_sizes, int n_in,
                              void* d_out, int out_size)
{
    const float* x     = (const float*)d_in[0];
    const float* w_in  = (const float*)d_in[1];
    const float* b_in  = (const float*)d_in[2];
    const float* w_out = (const float*)d_in[3];
    const float* b_out = (const float*)d_in[4];
    const int*   cmask = (const int*)d_in[5];

    __half *qkv, *att, *xh, *w1h, *w2h;
    cudaGetSymbolAddress((void**)&qkv, g_qkv);
    cudaGetSymbolAddress((void**)&att, g_att);
    cudaGetSymbolAddress((void**)&xh,  g_xh);
    cudaGetSymbolAddress((void**)&w1h, g_w1h);
    cudaGetSymbolAddress((void**)&w2h, g_w2h);

    cudaFuncSetAttribute((const void*)gemm_f16mma<1>,
                         cudaFuncAttributeMaxDynamicSharedMemorySize, GSMEM_BYTES);
    cudaFuncSetAttribute((const void*)gemm_f16mma<0>,
                         cudaFuncAttributeMaxDynamicSharedMemorySize, GSMEM_BYTES);
    cudaFuncSetAttribute((const void*)flash_attn_f16,
                         cudaFuncAttributeMaxDynamicSharedMemorySize, ASMEM_BYTES);

    // 0) convert x, w_in, w_out to fp16 (one launch)
    {
        int tot = MROWS * DD / 4 + N1 * DD / 4 + DD * DD / 4;
        toh3<<<(tot + 255) / 256, 256>>>(x, xh, w_in, w1h, w_out, w2h);
    }

    // 1) QKV projection -> fp16 qkv
    gemm_f16mma<1><<<dim3(N1 / 128, MROWS / 128), 256, GSMEM_BYTES>>>(
        xh, w1h, b_in, qkv, MROWS, N1, DD);

    // 2) Causal multi-head flash attention (fp16 TC, f16x2 softmax exp)
    flash_attn_f16<<<dim3(SS / QT, HH, BB), 256, ASMEM_BYTES>>>(cmask);

    // 3) Output projection -> fp32 out
    gemm_f16mma<0><<<dim3(DD / 128, MROWS / 128), 256, GSMEM_BYTES>>>(
        att, w2h, b_out, (float*)d_out, MROWS, DD, DD);
}